// round 1
// baseline (speedup 1.0000x reference)
#include <cuda_runtime.h>
#include <stdint.h>

#define N_PART 32768
#define N_CENT 2048
// SC = -log2(e)/tau, tau = 1e-3
#define SC_CONST (-1442.6950408889634f)

__device__ float4 d_cabc[N_CENT];          // (A,B,C,0) per centroid, exp2-domain
__device__ float4 d_p4[N_PART];            // (x0, x1, umax, w/Z)
__device__ float2 d_p2[N_PART];            // (x0*w/Z, x1*w/Z)
__device__ float  d_acc[3 * N_CENT];       // accX | accY | accW

__device__ __forceinline__ float fast_exp2(float x) {
    float r;
    asm("ex2.approx.ftz.f32 %0, %1;" : "=f"(r) : "f"(x));
    return r;
}

// ---------------------------------------------------------------------------
// Kernel 1 (single block, 1024 thr): exact top-2048 by weight (jax.lax.top_k
// semantics incl. tie order), emit exp2-domain centroid constants. Also zeros
// the global accumulators.
// ---------------------------------------------------------------------------
__global__ void k_topk(const float* __restrict__ x, const float* __restrict__ w) {
    __shared__ unsigned hist[256];
    __shared__ unsigned s_prefix, s_k, s_cnt;
    __shared__ unsigned long long keys[4096];
    const int tid = threadIdx.x;

    // zero accumulators for this launch
    for (int i = tid; i < 3 * N_CENT; i += 1024) d_acc[i] = 0.0f;

    // ---- radix select (4 x 8-bit passes, high->low) on float bits ----
    unsigned prefix = 0;
    unsigned kk = N_CENT;
    for (int pass = 0; pass < 4; ++pass) {
        const int shift = 24 - 8 * pass;
        if (tid < 256) hist[tid] = 0;
        __syncthreads();
        for (int i = tid; i < N_PART; i += 1024) {
            unsigned b = __float_as_uint(w[i]);   // w >= 0 -> bits monotone
            bool ok = (pass == 0) || ((b >> (shift + 8)) == prefix);
            if (ok) atomicAdd(&hist[(b >> shift) & 255u], 1u);
        }
        __syncthreads();
        if (tid == 0) {
            unsigned cum = 0;
            int d = 255;
            while (d > 0 && cum + hist[d] < kk) { cum += hist[d]; --d; }
            s_prefix = (prefix << 8) | (unsigned)d;
            s_k = kk - cum;
        }
        __syncthreads();
        prefix = s_prefix;
        kk = s_k;
        __syncthreads();
    }
    const unsigned T = prefix;   // bits of the 2048-th largest value

    // ---- collect all candidates with bits >= T ----
    if (tid == 0) s_cnt = 0;
    __syncthreads();
    for (int i = tid; i < N_PART; i += 1024) {
        unsigned b = __float_as_uint(w[i]);
        if (b >= T) {
            unsigned p = atomicAdd(&s_cnt, 1u);
            if (p < 4096u) keys[p] = ((unsigned long long)b << 32) | (unsigned)(~i);
        }
    }
    __syncthreads();
    const unsigned total = min(s_cnt, 4096u);
    for (int i = tid; i < 4096; i += 1024)
        if ((unsigned)i >= total) keys[i] = 0ull;
    __syncthreads();

    // ---- bitonic sort, descending (ties: larger ~i == smaller index first) ----
    for (int size = 2; size <= 4096; size <<= 1) {
        for (int stride = size >> 1; stride > 0; stride >>= 1) {
            for (int i = tid; i < 2048; i += 1024) {
                int idx = ((i & ~(stride - 1)) << 1) | (i & (stride - 1));
                int prt = idx | stride;
                unsigned long long A = keys[idx], B = keys[prt];
                bool desc = ((idx & size) == 0);
                if ((A < B) == desc) { keys[idx] = B; keys[prt] = A; }
            }
            __syncthreads();
        }
    }

    // ---- emit centroid constants (exp2 domain) ----
    for (int m = tid; m < N_CENT; m += 1024) {
        unsigned idx = ~((unsigned)(keys[m] & 0xFFFFFFFFull));
        float cx = x[2 * idx], cy = x[2 * idx + 1];
        float A = SC_CONST * (-2.0f * cx);
        float B = SC_CONST * (-2.0f * cy);
        float C = SC_CONST * (cx * cx + cy * cy);
        d_cabc[m] = make_float4(A, B, C, 0.0f);
    }
}

// ---------------------------------------------------------------------------
// Kernel 2: per particle, two tight loops over all 2048 centroids:
//   (a) umax = max_m u,  (b) Z = sum exp2(u - umax)  (exact softmax norm)
// Stores particle record for the gather pass.
// 256 blocks x 128 threads, 1 particle per thread.
// ---------------------------------------------------------------------------
__global__ void k_pass2(const float* __restrict__ x, const float* __restrict__ w) {
    __shared__ float4 sc[N_CENT];   // 32 KB
    const int tid = threadIdx.x;
    for (int j = tid; j < N_CENT; j += 128) sc[j] = d_cabc[j];
    __syncthreads();

    const int n = blockIdx.x * 128 + tid;
    const float x0 = x[2 * n], x1 = x[2 * n + 1], wn = w[n];

    // loop 1: max
    float um0 = -1e30f, um1 = -1e30f, um2 = -1e30f, um3 = -1e30f;
    for (int m = 0; m < N_CENT; m += 4) {
        float4 c0 = sc[m + 0], c1 = sc[m + 1], c2 = sc[m + 2], c3 = sc[m + 3];
        um0 = fmaxf(um0, fmaf(c0.x, x0, fmaf(c0.y, x1, c0.z)));
        um1 = fmaxf(um1, fmaf(c1.x, x0, fmaf(c1.y, x1, c1.z)));
        um2 = fmaxf(um2, fmaf(c2.x, x0, fmaf(c2.y, x1, c2.z)));
        um3 = fmaxf(um3, fmaf(c3.x, x0, fmaf(c3.y, x1, c3.z)));
    }
    const float umax = fmaxf(fmaxf(um0, um1), fmaxf(um2, um3));

    // loop 2: Z
    float z0 = 0.f, z1 = 0.f, z2 = 0.f, z3 = 0.f;
    for (int m = 0; m < N_CENT; m += 4) {
        float4 c0 = sc[m + 0], c1 = sc[m + 1], c2 = sc[m + 2], c3 = sc[m + 3];
        z0 += fast_exp2(fmaf(c0.x, x0, fmaf(c0.y, x1, c0.z)) - umax);
        z1 += fast_exp2(fmaf(c1.x, x0, fmaf(c1.y, x1, c1.z)) - umax);
        z2 += fast_exp2(fmaf(c2.x, x0, fmaf(c2.y, x1, c2.z)) - umax);
        z3 += fast_exp2(fmaf(c3.x, x0, fmaf(c3.y, x1, c3.z)) - umax);
    }
    const float Z = (z0 + z1) + (z2 + z3);
    const float pw = wn / Z;

    d_p4[n] = make_float4(x0, x1, umax, pw);
    d_p2[n] = make_float2(x0 * pw, x1 * pw);
}

// ---------------------------------------------------------------------------
// Kernel 3: gather per centroid (register accumulators, no hot atomics).
// 256 blocks x 256 threads: blockIdx = (chunk<<3)|group; thread = centroid.
// Each block streams a 1024-particle chunk through smem (LDS broadcast).
// ---------------------------------------------------------------------------
__global__ void k_pass3() {
    __shared__ float4 sp4[1024];   // 16 KB
    __shared__ float2 sp2[1024];   // 8 KB
    const int tid = threadIdx.x;
    const int g = blockIdx.x & 7;
    const int chunk = blockIdx.x >> 3;
    const int m = g * 256 + tid;
    const float4 cc = d_cabc[m];
    const int base = chunk * 1024;

    for (int j = tid; j < 1024; j += 256) {
        sp4[j] = d_p4[base + j];
        sp2[j] = d_p2[base + j];
    }
    __syncthreads();

    float a0 = 0.f, a1 = 0.f, a2 = 0.f;
#pragma unroll 4
    for (int j = 0; j < 1024; ++j) {
        float4 p = sp4[j];
        float u = fmaf(cc.x, p.x, fmaf(cc.y, p.y, cc.z));
        float e = fast_exp2(u - p.z);        // u <= umax (identical fma form) -> e in [0,1]
        float2 q = sp2[j];
        a0 = fmaf(e, q.x, a0);
        a1 = fmaf(e, q.y, a1);
        a2 = fmaf(e, p.w, a2);
    }

    atomicAdd(&d_acc[m], a0);
    atomicAdd(&d_acc[N_CENT + m], a1);
    atomicAdd(&d_acc[2 * N_CENT + m], a2);
}

// ---------------------------------------------------------------------------
// Kernel 4: finalize y = num/den, v = den.
// Output layout: y (2048 x 2, row-major) then v (2048).
// ---------------------------------------------------------------------------
__global__ void k_final(float* __restrict__ out) {
    const int m = blockIdx.x * 256 + threadIdx.x;
    if (m < N_CENT) {
        float nx = d_acc[m];
        float ny = d_acc[N_CENT + m];
        float den = d_acc[2 * N_CENT + m];
        out[2 * m + 0] = nx / den;
        out[2 * m + 1] = ny / den;
        out[2 * N_CENT + m] = den;
    }
}

extern "C" void kernel_launch(void* const* d_in, const int* in_sizes, int n_in,
                              void* d_out, int out_size) {
    const float* x = (const float*)d_in[0];   // [32768, 2]
    const float* w = (const float*)d_in[1];   // [32768]
    float* out = (float*)d_out;               // 6144 floats: y (4096) then v (2048)

    k_topk<<<1, 1024>>>(x, w);
    k_pass2<<<256, 128>>>(x, w);
    k_pass3<<<256, 256>>>();
    k_final<<<8, 256>>>(out);
}

// round 2
// speedup vs baseline: 1.1202x; 1.1202x over previous
#include <cuda_runtime.h>
#include <stdint.h>

#define N_PART 32768
#define N_CENT 2048
// SC = -log2(e)/tau, tau = 1e-3
#define SC_CONST (-1442.6950408889634f)
#define NSPLIT 4
#define CSPL (N_CENT / NSPLIT)   // 512 centroids per split

__device__ float4 d_cabc[N_CENT];            // (A,B,C,0) per centroid, exp2-domain
__device__ float4 d_p4[N_PART];              // (x0, x1, umax, w/Z)
__device__ float2 d_p2[N_PART];              // (x0*w/Z, x1*w/Z)
__device__ float  d_acc[3 * N_CENT];         // accX | accY | accW
__device__ float2 d_part[NSPLIT * N_PART];   // per-split (umax_local, Z_local)
__device__ unsigned long long d_cand[4096];  // compacted top-k candidates
__device__ unsigned d_gcnt;

__device__ __forceinline__ float fast_exp2(float x) {
    float r;
    asm("ex2.approx.ftz.f32 %0, %1;" : "=f"(r) : "f"(x));
    return r;
}

// ---------------------------------------------------------------------------
// Kernel 1 (single block): radix-select the top-2048 weight threshold, compact
// all candidates >= threshold to global. Also zeros the accumulators.
// ---------------------------------------------------------------------------
__global__ void __launch_bounds__(1024) k_thresh(const float* __restrict__ w) {
    __shared__ unsigned hist[256];
    __shared__ unsigned s_prefix, s_k;
    const int tid = threadIdx.x;

    if (tid == 0) d_gcnt = 0;
    for (int i = tid; i < 3 * N_CENT; i += 1024) d_acc[i] = 0.0f;

    // ---- radix select (4 x 8-bit passes, high->low) on float bits ----
    unsigned prefix = 0;
    unsigned kk = N_CENT;
    for (int pass = 0; pass < 4; ++pass) {
        const int shift = 24 - 8 * pass;
        if (tid < 256) hist[tid] = 0;
        __syncthreads();
        for (int i = tid; i < N_PART; i += 1024) {
            unsigned b = __float_as_uint(w[i]);   // w >= 0 -> bits monotone
            bool ok = (pass == 0) || ((b >> (shift + 8)) == prefix);
            if (ok) atomicAdd(&hist[(b >> shift) & 255u], 1u);
        }
        __syncthreads();
        if (tid == 0) {
            unsigned cum = 0;
            int d = 255;
            while (d > 0 && cum + hist[d] < kk) { cum += hist[d]; --d; }
            s_prefix = (prefix << 8) | (unsigned)d;
            s_k = kk - cum;
        }
        __syncthreads();
        prefix = s_prefix;
        kk = s_k;
        __syncthreads();
    }
    const unsigned T = prefix;   // bits of the 2048-th largest value

    // ---- compact all candidates with bits >= T to global ----
    for (int i = tid; i < N_PART; i += 1024) {
        unsigned b = __float_as_uint(w[i]);
        if (b >= T) {
            unsigned p = atomicAdd(&d_gcnt, 1u);
            if (p < 4096u)
                d_cand[p] = ((unsigned long long)b << 32) | (unsigned)(~i);
        }
    }
}

// ---------------------------------------------------------------------------
// Kernel 2 (grid-wide): rank each candidate by counting strictly-greater keys
// (keys unique: index embedded). rank < 2048 -> emit centroid constants in
// exact jax.lax.top_k order (desc weight, ties -> lower index).
// One warp per candidate, lanes split the comparisons.
// ---------------------------------------------------------------------------
__global__ void __launch_bounds__(512) k_rank(const float* __restrict__ x) {
    __shared__ unsigned long long keys[4096];
    const int tid = threadIdx.x;
    const unsigned C = min(d_gcnt, 4096u);

    for (int j = tid; j < (int)C; j += 512) keys[j] = d_cand[j];
    __syncthreads();

    const int lane = tid & 31;
    const int wslot = blockIdx.x * 16 + (tid >> 5);   // 256 warp slots

    for (int c = wslot; c < (int)C; c += 256) {
        const unsigned long long key = keys[c];
        int r = 0;
        for (int j = lane; j < (int)C; j += 32) r += (keys[j] > key);
        r = __reduce_add_sync(0xffffffffu, r);
        if (lane == 0 && r < N_CENT) {
            unsigned idx = ~((unsigned)(key & 0xFFFFFFFFull));
            float cx = x[2 * idx], cy = x[2 * idx + 1];
            float A = SC_CONST * (-2.0f * cx);
            float B = SC_CONST * (-2.0f * cy);
            float Cc = SC_CONST * (cx * cx + cy * cy);
            d_cabc[r] = make_float4(A, B, Cc, 0.0f);
        }
    }
}

// ---------------------------------------------------------------------------
// Kernel 3: per-particle max & Z over a 512-centroid SPLIT (4-way split ->
// 4096 warps for latency hiding). blockIdx.x = particle block, .y = split.
// ---------------------------------------------------------------------------
__global__ void __launch_bounds__(128) k_pass2(const float* __restrict__ x) {
    __shared__ float4 sc[CSPL];   // 8 KB
    const int tid = threadIdx.x;
    const int split = blockIdx.y;
    for (int j = tid; j < CSPL; j += 128) sc[j] = d_cabc[split * CSPL + j];
    __syncthreads();

    const int n = blockIdx.x * 128 + tid;
    const float2 xn = ((const float2*)x)[n];
    const float x0 = xn.x, x1 = xn.y;

    // loop 1: max over this split
    float um0 = -1e30f, um1 = -1e30f, um2 = -1e30f, um3 = -1e30f;
    for (int m = 0; m < CSPL; m += 4) {
        float4 c0 = sc[m + 0], c1 = sc[m + 1], c2 = sc[m + 2], c3 = sc[m + 3];
        um0 = fmaxf(um0, fmaf(c0.x, x0, fmaf(c0.y, x1, c0.z)));
        um1 = fmaxf(um1, fmaf(c1.x, x0, fmaf(c1.y, x1, c1.z)));
        um2 = fmaxf(um2, fmaf(c2.x, x0, fmaf(c2.y, x1, c2.z)));
        um3 = fmaxf(um3, fmaf(c3.x, x0, fmaf(c3.y, x1, c3.z)));
    }
    const float um = fmaxf(fmaxf(um0, um1), fmaxf(um2, um3));

    // loop 2: Z over this split (relative to split-local max; no overflow)
    float z0 = 0.f, z1 = 0.f, z2 = 0.f, z3 = 0.f;
    for (int m = 0; m < CSPL; m += 4) {
        float4 c0 = sc[m + 0], c1 = sc[m + 1], c2 = sc[m + 2], c3 = sc[m + 3];
        z0 += fast_exp2(fmaf(c0.x, x0, fmaf(c0.y, x1, c0.z)) - um);
        z1 += fast_exp2(fmaf(c1.x, x0, fmaf(c1.y, x1, c1.z)) - um);
        z2 += fast_exp2(fmaf(c2.x, x0, fmaf(c2.y, x1, c2.z)) - um);
        z3 += fast_exp2(fmaf(c3.x, x0, fmaf(c3.y, x1, c3.z)) - um);
    }
    d_part[split * N_PART + n] = make_float2(um, (z0 + z1) + (z2 + z3));
}

// ---------------------------------------------------------------------------
// Kernel 4: combine the 4 split partials into the particle record.
//   Z = sum_i Z_i * exp2(m_i - m),  m = max_i m_i
// ---------------------------------------------------------------------------
__global__ void __launch_bounds__(256) k_combine(const float* __restrict__ x,
                                                const float* __restrict__ w) {
    const int n = blockIdx.x * 256 + threadIdx.x;
    float2 p0 = d_part[0 * N_PART + n];
    float2 p1 = d_part[1 * N_PART + n];
    float2 p2 = d_part[2 * N_PART + n];
    float2 p3 = d_part[3 * N_PART + n];
    const float m = fmaxf(fmaxf(p0.x, p1.x), fmaxf(p2.x, p3.x));
    const float Z = p0.y * fast_exp2(p0.x - m) + p1.y * fast_exp2(p1.x - m)
                  + p2.y * fast_exp2(p2.x - m) + p3.y * fast_exp2(p3.x - m);
    const float2 xn = ((const float2*)x)[n];
    const float pw = w[n] / Z;
    d_p4[n] = make_float4(xn.x, xn.y, m, pw);
    d_p2[n] = make_float2(xn.x * pw, xn.y * pw);
}

// ---------------------------------------------------------------------------
// Kernel 5: gather per centroid, register accumulators.
// 512 blocks x 256 threads: blockIdx = (chunk<<3)|group; thread = centroid.
// Each block streams a 512-particle chunk through smem (LDS broadcast).
// ---------------------------------------------------------------------------
__global__ void __launch_bounds__(256) k_pass3() {
    __shared__ float4 sp4[512];   // 8 KB
    __shared__ float2 sp2[512];   // 4 KB
    const int tid = threadIdx.x;
    const int g = blockIdx.x & 7;
    const int chunk = blockIdx.x >> 3;
    const int m = g * 256 + tid;
    const float4 cc = d_cabc[m];
    const int base = chunk * 512;

    for (int j = tid; j < 512; j += 256) {
        sp4[j] = d_p4[base + j];
        sp2[j] = d_p2[base + j];
    }
    __syncthreads();

    float a0 = 0.f, a1 = 0.f, a2 = 0.f;
#pragma unroll 8
    for (int j = 0; j < 512; ++j) {
        float4 p = sp4[j];
        float u = fmaf(cc.x, p.x, fmaf(cc.y, p.y, cc.z));
        float e = fast_exp2(u - p.z);        // u <= umax -> e in [0,1]
        float2 q = sp2[j];
        a0 = fmaf(e, q.x, a0);
        a1 = fmaf(e, q.y, a1);
        a2 = fmaf(e, p.w, a2);
    }

    atomicAdd(&d_acc[m], a0);
    atomicAdd(&d_acc[N_CENT + m], a1);
    atomicAdd(&d_acc[2 * N_CENT + m], a2);
}

// ---------------------------------------------------------------------------
// Kernel 6: finalize y = num/den, v = den.
// ---------------------------------------------------------------------------
__global__ void __launch_bounds__(256) k_final(float* __restrict__ out) {
    const int m = blockIdx.x * 256 + threadIdx.x;
    if (m < N_CENT) {
        float nx = d_acc[m];
        float ny = d_acc[N_CENT + m];
        float den = d_acc[2 * N_CENT + m];
        out[2 * m + 0] = nx / den;
        out[2 * m + 1] = ny / den;
        out[2 * N_CENT + m] = den;
    }
}

extern "C" void kernel_launch(void* const* d_in, const int* in_sizes, int n_in,
                              void* d_out, int out_size) {
    const float* x = (const float*)d_in[0];   // [32768, 2]
    const float* w = (const float*)d_in[1];   // [32768]
    float* out = (float*)d_out;               // 6144 floats: y (4096) then v (2048)

    k_thresh<<<1, 1024>>>(w);
    k_rank<<<16, 512>>>(x);
    k_pass2<<<dim3(256, NSPLIT), 128>>>(x);
    k_combine<<<128, 256>>>(x, w);
    k_pass3<<<512, 256>>>();
    k_final<<<8, 256>>>(out);
}